// round 1
// baseline (speedup 1.0000x reference)
#include <cuda_runtime.h>
#include <math.h>

// Problem constants
#define Bn   8
#define Ln   4096
#define DINn 64
#define Dn   256
#define NLn  2
#define DIn  512
#define DSn  16
#define DCn  4
#define DTRn 16
#define Mrows (Bn * Ln)   // 32768

// ---------------------------------------------------------------------------
// Scratch (device globals — no runtime allocation allowed)
// ---------------------------------------------------------------------------
__device__ float g_h   [Mrows * Dn];        // 8.39M
__device__ float g_t0  [Mrows * Dn];        // 8.39M
__device__ float g_xz  [Mrows * 2 * DIn];   // 33.55M
__device__ float g_u   [Mrows * DIn];       // 16.78M
__device__ float g_dt  [Mrows * DIn];       // 16.78M
__device__ float g_xdbc[Mrows * 48];        // 1.57M
__device__ float g_y   [Mrows * DIn];       // 16.78M

// ---------------------------------------------------------------------------
// Helpers
// ---------------------------------------------------------------------------
__device__ __forceinline__ float softplus_f(float x) {
    return fmaxf(x, 0.f) + log1pf(__expf(-fabsf(x)));
}
__device__ __forceinline__ float silu_f(float x) {
    return x / (1.f + __expf(-x));
}

// ---------------------------------------------------------------------------
// Generic SGEMM: C[M,N] = A[M,K] (row-major, lda) * W[N,K]^T (row-major)
// M is always 32768 (multiple of 128). N, K arbitrary (K % 8 == 0, lda % 4 == 0).
// EPI: 0 = store, 1 = +bias, 2 = softplus(+bias)
// Tile 128x128x8, 256 threads, 8x8 per-thread microtile, 4+4 split layout.
// ---------------------------------------------------------------------------
template <int EPI>
__global__ void __launch_bounds__(256, 2) sgemm_nt(
    int N, int K,
    const float* __restrict__ A, int lda,
    const float* __restrict__ W,
    const float* __restrict__ bias,
    float* __restrict__ C, int ldc)
{
    __shared__ __align__(16) float As[8][132];
    __shared__ __align__(16) float Ws[8][132];

    const int tid = threadIdx.x;
    const int tx = tid & 15;
    const int ty = tid >> 4;
    const int m0 = blockIdx.y * 128;
    const int n0 = blockIdx.x * 128;

    const int lr = tid >> 1;        // 0..127
    const int lk = (tid & 1) * 4;   // 0 or 4

    float acc[8][8];
    #pragma unroll
    for (int i = 0; i < 8; i++)
        #pragma unroll
        for (int j = 0; j < 8; j++) acc[i][j] = 0.f;

    const float* Aptr = A + (size_t)(m0 + lr) * lda + lk;
    const int wn = n0 + lr;
    const float* Wptr = W + (size_t)wn * K + lk;
    const bool wok = (wn < N);

    for (int k0 = 0; k0 < K; k0 += 8) {
        float4 av = *(const float4*)(Aptr + k0);
        As[lk + 0][lr] = av.x; As[lk + 1][lr] = av.y;
        As[lk + 2][lr] = av.z; As[lk + 3][lr] = av.w;

        float4 wv = make_float4(0.f, 0.f, 0.f, 0.f);
        if (wok) wv = *(const float4*)(Wptr + k0);
        Ws[lk + 0][lr] = wv.x; Ws[lk + 1][lr] = wv.y;
        Ws[lk + 2][lr] = wv.z; Ws[lk + 3][lr] = wv.w;

        __syncthreads();
        #pragma unroll
        for (int k = 0; k < 8; k++) {
            float a[8], bb[8];
            *(float4*)&a[0]  = *(const float4*)&As[k][ty * 4];
            *(float4*)&a[4]  = *(const float4*)&As[k][64 + ty * 4];
            *(float4*)&bb[0] = *(const float4*)&Ws[k][tx * 4];
            *(float4*)&bb[4] = *(const float4*)&Ws[k][64 + tx * 4];
            #pragma unroll
            for (int i = 0; i < 8; i++)
                #pragma unroll
                for (int j = 0; j < 8; j++)
                    acc[i][j] = fmaf(a[i], bb[j], acc[i][j]);
        }
        __syncthreads();
    }

    #pragma unroll
    for (int i = 0; i < 8; i++) {
        const int r = m0 + ((i < 4) ? (ty * 4 + i) : (64 + ty * 4 + i - 4));
        #pragma unroll
        for (int j = 0; j < 8; j++) {
            const int c = n0 + ((j < 4) ? (tx * 4 + j) : (64 + tx * 4 + j - 4));
            if (c < N) {
                float v = acc[i][j];
                if (EPI >= 1) v += bias[c];
                if (EPI == 2) v = softplus_f(v);
                C[(size_t)r * ldc + c] = v;
            }
        }
    }
}

// ---------------------------------------------------------------------------
// Depthwise causal conv (DC=4) + bias + SiLU.  Reads u-half of g_xz.
// ---------------------------------------------------------------------------
__global__ void conv_silu_kernel(const float* __restrict__ xz,
                                 const float* __restrict__ w,
                                 const float* __restrict__ cb,
                                 float* __restrict__ u)
{
    const int idx = blockIdx.x * blockDim.x + threadIdx.x;
    if (idx >= Mrows * DIn) return;
    const int d  = idx & (DIn - 1);
    const int bl = idx >> 9;
    const int l  = bl & (Ln - 1);
    float acc = cb[d];
    #pragma unroll
    for (int k = 0; k < 4; k++) {
        const int ll = l - 3 + k;
        if (ll >= 0)
            acc = fmaf(w[d * 4 + k], xz[(size_t)(bl - 3 + k) * (2 * DIn) + d], acc);
    }
    u[idx] = silu_f(acc);
}

// ---------------------------------------------------------------------------
// LayerNorm over last dim (256), one block per row, in -> out.
// ---------------------------------------------------------------------------
__global__ void ln256_kernel(const float* __restrict__ in, float* __restrict__ out,
                             const float* __restrict__ g, const float* __restrict__ b)
{
    const int row = blockIdx.x;
    const int t = threadIdx.x;
    const float v = in[(size_t)row * 256 + t];
    float s = v, sq = v * v;
    #pragma unroll
    for (int o = 16; o > 0; o >>= 1) {
        s  += __shfl_xor_sync(~0u, s, o);
        sq += __shfl_xor_sync(~0u, sq, o);
    }
    __shared__ float ss[8], ssq[8];
    if ((t & 31) == 0) { ss[t >> 5] = s; ssq[t >> 5] = sq; }
    __syncthreads();
    float tot = 0.f, totq = 0.f;
    #pragma unroll
    for (int i = 0; i < 8; i++) { tot += ss[i]; totq += ssq[i]; }
    const float mean = tot * (1.f / 256.f);
    const float var  = totq * (1.f / 256.f) - mean * mean;
    const float rstd = rsqrtf(var + 1e-5f);
    out[(size_t)row * 256 + t] = (v - mean) * rstd * g[t] + b[t];
}

// ---------------------------------------------------------------------------
// Selective scan, fused with  (+u*Dp) * silu(z)  epilogue.
// Thread per (b,d,s): lane bits[0:4)=s, so shfl_xor {1,2,4,8} reduces over s.
// Block = 512 threads covers 32 d's x 16 s for one b; grid = B*16 = 128.
// 64-step smem-staged chunks; state h carried in a register.
// ---------------------------------------------------------------------------
#define SCH 64
__global__ void __launch_bounds__(512) scan_kernel(
    const float* __restrict__ u, const float* __restrict__ dt,
    const float* __restrict__ xz, const float* __restrict__ xdbc,
    const float* __restrict__ A_log, const float* __restrict__ Dp,
    float* __restrict__ y)
{
    __shared__ float s_dt[SCH][32], s_u[SCH][32], s_z[SCH][32], s_y[SCH][32];
    __shared__ float s_B[SCH][16], s_C[SCH][16];

    const int tid = threadIdx.x;
    const int b  = blockIdx.x >> 4;
    const int d0 = (blockIdx.x & 15) * 32;
    const int s  = tid & 15;
    const int dd = tid >> 4;       // 0..31
    const int d  = d0 + dd;

    const float A   = -__expf(A_log[d * DSn + s]);
    const float dpv = Dp[d];
    float h = 0.f;

    const size_t base_bl = (size_t)b * Ln;

    for (int l0 = 0; l0 < Ln; l0 += SCH) {
        for (int i = tid; i < SCH * 32; i += 512) {
            const int r = i >> 5, c = i & 31;
            const size_t bl = base_bl + l0 + r;
            s_dt[r][c] = dt[bl * DIn + d0 + c];
            s_u [r][c] = u [bl * DIn + d0 + c];
            s_z [r][c] = xz[bl * (2 * DIn) + DIn + d0 + c];
        }
        for (int i = tid; i < SCH * 16; i += 512) {
            const int r = i >> 4, c = i & 15;
            const size_t bl = base_bl + l0 + r;
            s_B[r][c] = xdbc[bl * 48 + 16 + c];
            s_C[r][c] = xdbc[bl * 48 + 32 + c];
        }
        __syncthreads();

        #pragma unroll 4
        for (int i = 0; i < SCH; i++) {
            const float dtv = s_dt[i][dd];
            const float uv  = s_u[i][dd];
            const float dA  = __expf(dtv * A);
            h = fmaf(h, dA, dtv * uv * s_B[i][s]);
            float yv = h * s_C[i][s];
            yv += __shfl_xor_sync(~0u, yv, 1);
            yv += __shfl_xor_sync(~0u, yv, 2);
            yv += __shfl_xor_sync(~0u, yv, 4);
            yv += __shfl_xor_sync(~0u, yv, 8);
            if (s == 0) {
                const float zv = s_z[i][dd];
                s_y[i][dd] = (yv + uv * dpv) * silu_f(zv);
            }
        }
        __syncthreads();

        for (int i = tid; i < SCH * 32; i += 512) {
            const int r = i >> 5, c = i & 31;
            y[(base_bl + l0 + r) * DIn + d0 + c] = s_y[r][c];
        }
        __syncthreads();
    }
}

// ---------------------------------------------------------------------------
// Attention pooling + final linear: one block per batch element.
// ---------------------------------------------------------------------------
__global__ void __launch_bounds__(1024) pool_kernel(
    const float* __restrict__ h, const float* __restrict__ wa,
    const float* __restrict__ ba, const float* __restrict__ Wf,
    const float* __restrict__ bf, float* __restrict__ out)
{
    __shared__ float s_logit[Ln];
    __shared__ float s_red[32];
    __shared__ float s_part[4 * 256];

    const int b = blockIdx.x, tid = threadIdx.x;
    const size_t base = (size_t)b * Ln * 256;

    // logits + running max
    float mx = -1e30f;
    for (int l = tid; l < Ln; l += 1024) {
        const float* row = h + base + (size_t)l * 256;
        float acc = 0.f;
        #pragma unroll 8
        for (int dd = 0; dd < 256; dd += 4) {
            const float4 hv = *(const float4*)(row + dd);
            const float4 wv = *(const float4*)(wa + dd);
            acc += hv.x * wv.x + hv.y * wv.y + hv.z * wv.z + hv.w * wv.w;
        }
        acc += ba[0];
        s_logit[l] = acc;
        mx = fmaxf(mx, acc);
    }
    #pragma unroll
    for (int o = 16; o > 0; o >>= 1) mx = fmaxf(mx, __shfl_xor_sync(~0u, mx, o));
    if ((tid & 31) == 0) s_red[tid >> 5] = mx;
    __syncthreads();
    if (tid < 32) {
        float v = s_red[tid];
        #pragma unroll
        for (int o = 16; o > 0; o >>= 1) v = fmaxf(v, __shfl_xor_sync(~0u, v, o));
        s_red[tid] = v;
    }
    __syncthreads();
    mx = s_red[0];

    // exp + sum
    float sum = 0.f;
    __syncthreads();
    for (int l = tid; l < Ln; l += 1024) {
        const float p = __expf(s_logit[l] - mx);
        s_logit[l] = p;
        sum += p;
    }
    #pragma unroll
    for (int o = 16; o > 0; o >>= 1) sum += __shfl_xor_sync(~0u, sum, o);
    __syncthreads();
    if ((tid & 31) == 0) s_red[tid >> 5] = sum;
    __syncthreads();
    if (tid < 32) {
        float v = s_red[tid];
        #pragma unroll
        for (int o = 16; o > 0; o >>= 1) v += __shfl_xor_sync(~0u, v, o);
        s_red[tid] = v;
    }
    __syncthreads();
    const float inv = 1.f / s_red[0];

    // pooled[d] = sum_l p[l]*h[l,d]
    const int chunk = tid >> 8;   // 0..3
    const int dch   = tid & 255;
    float acc = 0.f;
    for (int l = chunk * 1024; l < (chunk + 1) * 1024; l++)
        acc = fmaf(s_logit[l], h[base + (size_t)l * 256 + dch], acc);
    s_part[chunk * 256 + dch] = acc;
    __syncthreads();

    float val = 0.f;
    if (tid < 256) {
        const float pooled = (s_part[tid] + s_part[256 + tid] +
                              s_part[512 + tid] + s_part[768 + tid]) * inv;
        val = pooled * Wf[tid];
    }
    #pragma unroll
    for (int o = 16; o > 0; o >>= 1) val += __shfl_xor_sync(~0u, val, o);
    __syncthreads();
    if (tid < 256 && (tid & 31) == 0) s_red[tid >> 5] = val;
    __syncthreads();
    if (tid == 0) {
        float tot = 0.f;
        #pragma unroll
        for (int i = 0; i < 8; i++) tot += s_red[i];
        out[b] = tot + bf[0];
    }
}

// ---------------------------------------------------------------------------
// Launch
// ---------------------------------------------------------------------------
extern "C" void kernel_launch(void* const* d_in, const int* in_sizes, int n_in,
                              void* d_out, int out_size)
{
    const float* x      = (const float*)d_in[0];
    const float* Wp     = (const float*)d_in[1];
    const float* bp     = (const float*)d_in[2];
    const float* g0     = (const float*)d_in[3];
    const float* b0     = (const float*)d_in[4];
    const float* Wi     = (const float*)d_in[5];
    const float* conv_w = (const float*)d_in[6];
    const float* conv_b = (const float*)d_in[7];
    const float* Wx     = (const float*)d_in[8];
    const float* Wdt    = (const float*)d_in[9];
    const float* bdt    = (const float*)d_in[10];
    const float* A_log  = (const float*)d_in[11];
    const float* Dp     = (const float*)d_in[12];
    const float* Wo     = (const float*)d_in[13];
    const float* ln_g   = (const float*)d_in[14];
    const float* ln_b   = (const float*)d_in[15];
    const float* wa     = (const float*)d_in[16];
    const float* ba     = (const float*)d_in[17];
    const float* Wf     = (const float*)d_in[18];
    const float* bf     = (const float*)d_in[19];

    float *p_h, *p_t0, *p_xz, *p_u, *p_dt, *p_xdbc, *p_y;
    cudaGetSymbolAddress((void**)&p_h,    g_h);
    cudaGetSymbolAddress((void**)&p_t0,   g_t0);
    cudaGetSymbolAddress((void**)&p_xz,   g_xz);
    cudaGetSymbolAddress((void**)&p_u,    g_u);
    cudaGetSymbolAddress((void**)&p_dt,   g_dt);
    cudaGetSymbolAddress((void**)&p_xdbc, g_xdbc);
    cudaGetSymbolAddress((void**)&p_y,    g_y);

    const dim3 gm(1, Mrows / 128);   // grid.y = 256

    // input projection + LN
    sgemm_nt<1><<<dim3(2, 256), 256>>>(Dn, DINn, x, DINn, Wp, bp, p_t0, Dn);
    ln256_kernel<<<Mrows, 256>>>(p_t0, p_h, g0, b0);

    for (int l = 0; l < NLn; l++) {
        // xz = h @ Wi^T   (N=1024, K=256)
        sgemm_nt<0><<<dim3(8, 256), 256>>>(2 * DIn, Dn, p_h, Dn,
                                           Wi + (size_t)l * 2 * DIn * Dn,
                                           nullptr, p_xz, 2 * DIn);
        // depthwise causal conv + silu
        conv_silu_kernel<<<(Mrows * DIn) / 256, 256>>>(
            p_xz, conv_w + (size_t)l * DIn * DCn, conv_b + (size_t)l * DIn, p_u);
        // xdbc = u @ Wx^T   (N=48, K=512)
        sgemm_nt<0><<<dim3(1, 256), 256>>>(48, DIn, p_u, DIn,
                                           Wx + (size_t)l * 48 * DIn,
                                           nullptr, p_xdbc, 48);
        // dt = softplus(dtraw @ Wdt^T + bdt)   (N=512, K=16)
        sgemm_nt<2><<<dim3(4, 256), 256>>>(DIn, DTRn, p_xdbc, 48,
                                           Wdt + (size_t)l * DIn * DTRn,
                                           bdt + (size_t)l * DIn, p_dt, DIn);
        // selective scan + fused epilogue
        scan_kernel<<<Bn * 16, 512>>>(p_u, p_dt, p_xz, p_xdbc,
                                      A_log + (size_t)l * DIn * DSn,
                                      Dp + (size_t)l * DIn, p_y);
        // out = y @ Wo^T   (N=256, K=512), then LN
        sgemm_nt<0><<<dim3(2, 256), 256>>>(Dn, DIn, p_y, DIn,
                                           Wo + (size_t)l * Dn * DIn,
                                           nullptr, p_t0, Dn);
        ln256_kernel<<<Mrows, 256>>>(p_t0, p_h,
                                     ln_g + (size_t)l * Dn, ln_b + (size_t)l * Dn);
    }

    pool_kernel<<<Bn, 1024>>>(p_h, wa, ba, Wf, bf, (float*)d_out);
}

// round 2
// speedup vs baseline: 1.2379x; 1.2379x over previous
#include <cuda_runtime.h>
#include <math.h>

// Problem constants
#define Bn   8
#define Ln   4096
#define DINn 64
#define Dn   256
#define NLn  2
#define DIn  512
#define DSn  16
#define DCn  4
#define DTRn 16
#define Mrows (Bn * Ln)   // 32768

// ---------------------------------------------------------------------------
// Scratch (device globals — no runtime allocation allowed)
// ---------------------------------------------------------------------------
__device__ float g_h   [Mrows * Dn];
__device__ float g_t0  [Mrows * Dn];
__device__ float g_xz  [Mrows * 2 * DIn];
__device__ float g_u   [Mrows * DIn];
__device__ float g_dt  [Mrows * DIn];
__device__ float g_xdbc[Mrows * 48];
__device__ float g_y   [Mrows * DIn];

// ---------------------------------------------------------------------------
// Helpers
// ---------------------------------------------------------------------------
__device__ __forceinline__ float softplus_f(float x) {
    return fmaxf(x, 0.f) + log1pf(__expf(-fabsf(x)));
}
__device__ __forceinline__ float silu_f(float x) {
    return x / (1.f + __expf(-x));
}
__device__ __forceinline__ float to_tf32(float x) {
    float r;
    asm("cvt.rna.tf32.f32 %0, %1;" : "=f"(r) : "f"(x));
    return r;
}
__device__ __forceinline__ void mma8(float* d,
                                     float a0, float a1, float a2, float a3,
                                     float b0, float b1) {
    asm volatile(
        "mma.sync.aligned.m16n8k8.row.col.f32.tf32.tf32.f32 "
        "{%0,%1,%2,%3},{%4,%5,%6,%7},{%8,%9},{%0,%1,%2,%3};"
        : "+f"(d[0]), "+f"(d[1]), "+f"(d[2]), "+f"(d[3])
        : "r"(__float_as_uint(a0)), "r"(__float_as_uint(a1)),
          "r"(__float_as_uint(a2)), "r"(__float_as_uint(a3)),
          "r"(__float_as_uint(b0)), "r"(__float_as_uint(b1)));
}

// ---------------------------------------------------------------------------
// TF32 tensor-core GEMM: C[M,N] = A[M,K] (row-major, lda) * W[N,K]^T.
// Requires M%128==0, N%128==0, K%16==0, lda%4==0.
// Tile 128x128x16, 256 threads (8 warps, 2x4), warp tile 64x32 of m16n8k8.
// smem k-permuted layout: logical k -> phys (g*8 + 2*(k&3) + ((k&4)>>2))
// so fragment loads are float2 (pairs (c, c+4)). SPAD=24: conflict-free.
// EPI: 0 = store, 1 = +bias
// ---------------------------------------------------------------------------
#define SPAD 24
template <int EPI>
__global__ void __launch_bounds__(256, 2) tf32_gemm(
    int N, int K,
    const float* __restrict__ A, int lda,
    const float* __restrict__ W,
    const float* __restrict__ bias,
    float* __restrict__ C, int ldc)
{
    __shared__ float As[2][128][SPAD];
    __shared__ float Ws[2][128][SPAD];

    const int tid  = threadIdx.x;
    const int wid  = tid >> 5, lane = tid & 31;
    const int wm   = (wid >> 2) * 64;     // 0 or 64
    const int wn   = (wid & 3) * 32;      // 0,32,64,96
    const int gr   = lane >> 2;           // 0..7
    const int gc   = lane & 3;            // 0..3
    const int m0   = blockIdx.y * 128;
    const int n0   = blockIdx.x * 128;

    // loader: thread covers (row=tid>>2, j=tid&3) and (row+64, j)
    const int lr0 = tid >> 2;
    const int lj  = tid & 3;
    const int pb  = (lj & 2) * 4 + (lj & 1);   // permuted base col

    const float* Ag = A + (size_t)(m0 + lr0) * lda + lj * 4;
    const float* Wg = W + (size_t)(n0 + lr0) * K + lj * 4;

    float acc[4][4][4];
    #pragma unroll
    for (int i = 0; i < 4; i++)
        #pragma unroll
        for (int j = 0; j < 4; j++)
            #pragma unroll
            for (int t = 0; t < 4; t++) acc[i][j][t] = 0.f;

    float4 ra0, ra1, rw0, rw1;

    // prologue: stage k0 = 0
    ra0 = *(const float4*)(Ag);
    ra1 = *(const float4*)(Ag + (size_t)64 * lda);
    rw0 = *(const float4*)(Wg);
    rw1 = *(const float4*)(Wg + (size_t)64 * K);
    {
        As[0][lr0     ][pb]     = to_tf32(ra0.x);
        As[0][lr0     ][pb + 2] = to_tf32(ra0.y);
        As[0][lr0     ][pb + 4] = to_tf32(ra0.z);
        As[0][lr0     ][pb + 6] = to_tf32(ra0.w);
        As[0][lr0 + 64][pb]     = to_tf32(ra1.x);
        As[0][lr0 + 64][pb + 2] = to_tf32(ra1.y);
        As[0][lr0 + 64][pb + 4] = to_tf32(ra1.z);
        As[0][lr0 + 64][pb + 6] = to_tf32(ra1.w);
        Ws[0][lr0     ][pb]     = to_tf32(rw0.x);
        Ws[0][lr0     ][pb + 2] = to_tf32(rw0.y);
        Ws[0][lr0     ][pb + 4] = to_tf32(rw0.z);
        Ws[0][lr0     ][pb + 6] = to_tf32(rw0.w);
        Ws[0][lr0 + 64][pb]     = to_tf32(rw1.x);
        Ws[0][lr0 + 64][pb + 2] = to_tf32(rw1.y);
        Ws[0][lr0 + 64][pb + 4] = to_tf32(rw1.z);
        Ws[0][lr0 + 64][pb + 6] = to_tf32(rw1.w);
    }
    __syncthreads();

    int buf = 0;
    for (int k0 = 16; k0 < K; k0 += 16) {
        // prefetch next tile into registers
        ra0 = *(const float4*)(Ag + k0);
        ra1 = *(const float4*)(Ag + (size_t)64 * lda + k0);
        rw0 = *(const float4*)(Wg + k0);
        rw1 = *(const float4*)(Wg + (size_t)64 * K + k0);

        // compute current buffer
        #pragma unroll
        for (int ks = 0; ks < 2; ks++) {
            float2 alo[4], ahi[4], bfr[4];
            #pragma unroll
            for (int fm = 0; fm < 4; fm++) {
                alo[fm] = *(const float2*)&As[buf][wm + fm * 16 + gr    ][ks * 8 + 2 * gc];
                ahi[fm] = *(const float2*)&As[buf][wm + fm * 16 + gr + 8][ks * 8 + 2 * gc];
            }
            #pragma unroll
            for (int fn = 0; fn < 4; fn++)
                bfr[fn] = *(const float2*)&Ws[buf][wn + fn * 8 + gr][ks * 8 + 2 * gc];
            #pragma unroll
            for (int fm = 0; fm < 4; fm++)
                #pragma unroll
                for (int fn = 0; fn < 4; fn++)
                    mma8(acc[fm][fn], alo[fm].x, ahi[fm].x, alo[fm].y, ahi[fm].y,
                         bfr[fn].x, bfr[fn].y);
        }

        // stage into other buffer
        const int nb = buf ^ 1;
        As[nb][lr0     ][pb]     = to_tf32(ra0.x);
        As[nb][lr0     ][pb + 2] = to_tf32(ra0.y);
        As[nb][lr0     ][pb + 4] = to_tf32(ra0.z);
        As[nb][lr0     ][pb + 6] = to_tf32(ra0.w);
        As[nb][lr0 + 64][pb]     = to_tf32(ra1.x);
        As[nb][lr0 + 64][pb + 2] = to_tf32(ra1.y);
        As[nb][lr0 + 64][pb + 4] = to_tf32(ra1.z);
        As[nb][lr0 + 64][pb + 6] = to_tf32(ra1.w);
        Ws[nb][lr0     ][pb]     = to_tf32(rw0.x);
        Ws[nb][lr0     ][pb + 2] = to_tf32(rw0.y);
        Ws[nb][lr0     ][pb + 4] = to_tf32(rw0.z);
        Ws[nb][lr0     ][pb + 6] = to_tf32(rw0.w);
        Ws[nb][lr0 + 64][pb]     = to_tf32(rw1.x);
        Ws[nb][lr0 + 64][pb + 2] = to_tf32(rw1.y);
        Ws[nb][lr0 + 64][pb + 4] = to_tf32(rw1.z);
        Ws[nb][lr0 + 64][pb + 6] = to_tf32(rw1.w);
        __syncthreads();
        buf = nb;
    }

    // last tile
    #pragma unroll
    for (int ks = 0; ks < 2; ks++) {
        float2 alo[4], ahi[4], bfr[4];
        #pragma unroll
        for (int fm = 0; fm < 4; fm++) {
            alo[fm] = *(const float2*)&As[buf][wm + fm * 16 + gr    ][ks * 8 + 2 * gc];
            ahi[fm] = *(const float2*)&As[buf][wm + fm * 16 + gr + 8][ks * 8 + 2 * gc];
        }
        #pragma unroll
        for (int fn = 0; fn < 4; fn++)
            bfr[fn] = *(const float2*)&Ws[buf][wn + fn * 8 + gr][ks * 8 + 2 * gc];
        #pragma unroll
        for (int fm = 0; fm < 4; fm++)
            #pragma unroll
            for (int fn = 0; fn < 4; fn++)
                mma8(acc[fm][fn], alo[fm].x, ahi[fm].x, alo[fm].y, ahi[fm].y,
                     bfr[fn].x, bfr[fn].y);
    }

    // epilogue
    #pragma unroll
    for (int fm = 0; fm < 4; fm++) {
        const int r0 = m0 + wm + fm * 16 + gr;
        #pragma unroll
        for (int fn = 0; fn < 4; fn++) {
            const int c0 = n0 + wn + fn * 8 + 2 * gc;
            float v0 = acc[fm][fn][0], v1 = acc[fm][fn][1];
            float v2 = acc[fm][fn][2], v3 = acc[fm][fn][3];
            if (EPI == 1) {
                v0 += bias[c0]; v1 += bias[c0 + 1];
                v2 += bias[c0]; v3 += bias[c0 + 1];
            }
            *(float2*)&C[(size_t)r0 * ldc + c0]       = make_float2(v0, v1);
            *(float2*)&C[(size_t)(r0 + 8) * ldc + c0] = make_float2(v2, v3);
        }
    }
}

// ---------------------------------------------------------------------------
// Fallback SIMT SGEMM for odd shapes (Wx: N=48; dt: K=16).
// C[M,N] = A[M,K]*W[N,K]^T.  EPI: 0 store, 1 +bias, 2 softplus(+bias)
// ---------------------------------------------------------------------------
template <int EPI>
__global__ void __launch_bounds__(256, 2) sgemm_nt(
    int N, int K,
    const float* __restrict__ A, int lda,
    const float* __restrict__ W,
    const float* __restrict__ bias,
    float* __restrict__ C, int ldc)
{
    __shared__ __align__(16) float As[8][132];
    __shared__ __align__(16) float Ws2[8][132];

    const int tid = threadIdx.x;
    const int tx = tid & 15;
    const int ty = tid >> 4;
    const int m0 = blockIdx.y * 128;
    const int n0 = blockIdx.x * 128;

    const int lr = tid >> 1;
    const int lk = (tid & 1) * 4;

    float acc[8][8];
    #pragma unroll
    for (int i = 0; i < 8; i++)
        #pragma unroll
        for (int j = 0; j < 8; j++) acc[i][j] = 0.f;

    const float* Aptr = A + (size_t)(m0 + lr) * lda + lk;
    const int wn = n0 + lr;
    const float* Wptr = W + (size_t)wn * K + lk;
    const bool wok = (wn < N);

    for (int k0 = 0; k0 < K; k0 += 8) {
        float4 av = *(const float4*)(Aptr + k0);
        As[lk + 0][lr] = av.x; As[lk + 1][lr] = av.y;
        As[lk + 2][lr] = av.z; As[lk + 3][lr] = av.w;

        float4 wv = make_float4(0.f, 0.f, 0.f, 0.f);
        if (wok) wv = *(const float4*)(Wptr + k0);
        Ws2[lk + 0][lr] = wv.x; Ws2[lk + 1][lr] = wv.y;
        Ws2[lk + 2][lr] = wv.z; Ws2[lk + 3][lr] = wv.w;

        __syncthreads();
        #pragma unroll
        for (int k = 0; k < 8; k++) {
            float a[8], bb[8];
            *(float4*)&a[0]  = *(const float4*)&As[k][ty * 4];
            *(float4*)&a[4]  = *(const float4*)&As[k][64 + ty * 4];
            *(float4*)&bb[0] = *(const float4*)&Ws2[k][tx * 4];
            *(float4*)&bb[4] = *(const float4*)&Ws2[k][64 + tx * 4];
            #pragma unroll
            for (int i = 0; i < 8; i++)
                #pragma unroll
                for (int j = 0; j < 8; j++)
                    acc[i][j] = fmaf(a[i], bb[j], acc[i][j]);
        }
        __syncthreads();
    }

    #pragma unroll
    for (int i = 0; i < 8; i++) {
        const int r = m0 + ((i < 4) ? (ty * 4 + i) : (64 + ty * 4 + i - 4));
        #pragma unroll
        for (int j = 0; j < 8; j++) {
            const int c = n0 + ((j < 4) ? (tx * 4 + j) : (64 + tx * 4 + j - 4));
            if (c < N) {
                float v = acc[i][j];
                if (EPI >= 1) v += bias[c];
                if (EPI == 2) v = softplus_f(v);
                C[(size_t)r * ldc + c] = v;
            }
        }
    }
}

// ---------------------------------------------------------------------------
// Depthwise causal conv (DC=4) + bias + SiLU.  Reads u-half of g_xz.
// ---------------------------------------------------------------------------
__global__ void conv_silu_kernel(const float* __restrict__ xz,
                                 const float* __restrict__ w,
                                 const float* __restrict__ cb,
                                 float* __restrict__ u)
{
    const int idx = blockIdx.x * blockDim.x + threadIdx.x;
    if (idx >= Mrows * DIn) return;
    const int d  = idx & (DIn - 1);
    const int bl = idx >> 9;
    const int l  = bl & (Ln - 1);
    float acc = cb[d];
    #pragma unroll
    for (int k = 0; k < 4; k++) {
        const int ll = l - 3 + k;
        if (ll >= 0)
            acc = fmaf(w[d * 4 + k], xz[(size_t)(bl - 3 + k) * (2 * DIn) + d], acc);
    }
    u[idx] = silu_f(acc);
}

// ---------------------------------------------------------------------------
// LayerNorm over last dim (256), one block per row.
// ---------------------------------------------------------------------------
__global__ void ln256_kernel(const float* __restrict__ in, float* __restrict__ out,
                             const float* __restrict__ g, const float* __restrict__ b)
{
    const int row = blockIdx.x;
    const int t = threadIdx.x;
    const float v = in[(size_t)row * 256 + t];
    float s = v, sq = v * v;
    #pragma unroll
    for (int o = 16; o > 0; o >>= 1) {
        s  += __shfl_xor_sync(~0u, s, o);
        sq += __shfl_xor_sync(~0u, sq, o);
    }
    __shared__ float ss[8], ssq[8];
    if ((t & 31) == 0) { ss[t >> 5] = s; ssq[t >> 5] = sq; }
    __syncthreads();
    float tot = 0.f, totq = 0.f;
    #pragma unroll
    for (int i = 0; i < 8; i++) { tot += ss[i]; totq += ssq[i]; }
    const float mean = tot * (1.f / 256.f);
    const float var  = totq * (1.f / 256.f) - mean * mean;
    const float rstd = rsqrtf(var + 1e-5f);
    out[(size_t)row * 256 + t] = (v - mean) * rstd * g[t] + b[t];
}

// ---------------------------------------------------------------------------
// Selective scan fused with (+u*Dp)*silu(z) epilogue.
// ---------------------------------------------------------------------------
#define SCH 64
__global__ void __launch_bounds__(512) scan_kernel(
    const float* __restrict__ u, const float* __restrict__ dt,
    const float* __restrict__ xz, const float* __restrict__ xdbc,
    const float* __restrict__ A_log, const float* __restrict__ Dp,
    float* __restrict__ y)
{
    __shared__ float s_dt[SCH][32], s_u[SCH][32], s_z[SCH][32], s_y[SCH][32];
    __shared__ float s_B[SCH][16], s_C[SCH][16];

    const int tid = threadIdx.x;
    const int b  = blockIdx.x >> 4;
    const int d0 = (blockIdx.x & 15) * 32;
    const int s  = tid & 15;
    const int dd = tid >> 4;
    const int d  = d0 + dd;

    const float A   = -__expf(A_log[d * DSn + s]);
    const float dpv = Dp[d];
    float h = 0.f;

    const size_t base_bl = (size_t)b * Ln;

    for (int l0 = 0; l0 < Ln; l0 += SCH) {
        for (int i = tid; i < SCH * 32; i += 512) {
            const int r = i >> 5, c = i & 31;
            const size_t bl = base_bl + l0 + r;
            s_dt[r][c] = dt[bl * DIn + d0 + c];
            s_u [r][c] = u [bl * DIn + d0 + c];
            s_z [r][c] = xz[bl * (2 * DIn) + DIn + d0 + c];
        }
        for (int i = tid; i < SCH * 16; i += 512) {
            const int r = i >> 4, c = i & 15;
            const size_t bl = base_bl + l0 + r;
            s_B[r][c] = xdbc[bl * 48 + 16 + c];
            s_C[r][c] = xdbc[bl * 48 + 32 + c];
        }
        __syncthreads();

        #pragma unroll 4
        for (int i = 0; i < SCH; i++) {
            const float dtv = s_dt[i][dd];
            const float uv  = s_u[i][dd];
            const float dA  = __expf(dtv * A);
            h = fmaf(h, dA, dtv * uv * s_B[i][s]);
            float yv = h * s_C[i][s];
            yv += __shfl_xor_sync(~0u, yv, 1);
            yv += __shfl_xor_sync(~0u, yv, 2);
            yv += __shfl_xor_sync(~0u, yv, 4);
            yv += __shfl_xor_sync(~0u, yv, 8);
            if (s == 0) {
                const float zv = s_z[i][dd];
                s_y[i][dd] = (yv + uv * dpv) * silu_f(zv);
            }
        }
        __syncthreads();

        for (int i = tid; i < SCH * 32; i += 512) {
            const int r = i >> 5, c = i & 31;
            y[(base_bl + l0 + r) * DIn + d0 + c] = s_y[r][c];
        }
        __syncthreads();
    }
}

// ---------------------------------------------------------------------------
// Attention pooling + final linear: one block per batch element.
// ---------------------------------------------------------------------------
__global__ void __launch_bounds__(1024) pool_kernel(
    const float* __restrict__ h, const float* __restrict__ wa,
    const float* __restrict__ ba, const float* __restrict__ Wf,
    const float* __restrict__ bf, float* __restrict__ out)
{
    __shared__ float s_logit[Ln];
    __shared__ float s_red[32];
    __shared__ float s_part[4 * 256];

    const int b = blockIdx.x, tid = threadIdx.x;
    const size_t base = (size_t)b * Ln * 256;

    float mx = -1e30f;
    for (int l = tid; l < Ln; l += 1024) {
        const float* row = h + base + (size_t)l * 256;
        float acc = 0.f;
        #pragma unroll 8
        for (int dd = 0; dd < 256; dd += 4) {
            const float4 hv = *(const float4*)(row + dd);
            const float4 wv = *(const float4*)(wa + dd);
            acc += hv.x * wv.x + hv.y * wv.y + hv.z * wv.z + hv.w * wv.w;
        }
        acc += ba[0];
        s_logit[l] = acc;
        mx = fmaxf(mx, acc);
    }
    #pragma unroll
    for (int o = 16; o > 0; o >>= 1) mx = fmaxf(mx, __shfl_xor_sync(~0u, mx, o));
    if ((tid & 31) == 0) s_red[tid >> 5] = mx;
    __syncthreads();
    if (tid < 32) {
        float v = s_red[tid];
        #pragma unroll
        for (int o = 16; o > 0; o >>= 1) v = fmaxf(v, __shfl_xor_sync(~0u, v, o));
        s_red[tid] = v;
    }
    __syncthreads();
    mx = s_red[0];

    float sum = 0.f;
    __syncthreads();
    for (int l = tid; l < Ln; l += 1024) {
        const float p = __expf(s_logit[l] - mx);
        s_logit[l] = p;
        sum += p;
    }
    #pragma unroll
    for (int o = 16; o > 0; o >>= 1) sum += __shfl_xor_sync(~0u, sum, o);
    __syncthreads();
    if ((tid & 31) == 0) s_red[tid >> 5] = sum;
    __syncthreads();
    if (tid < 32) {
        float v = s_red[tid];
        #pragma unroll
        for (int o = 16; o > 0; o >>= 1) v += __shfl_xor_sync(~0u, v, o);
        s_red[tid] = v;
    }
    __syncthreads();
    const float inv = 1.f / s_red[0];

    const int chunk = tid >> 8;
    const int dch   = tid & 255;
    float acc = 0.f;
    for (int l = chunk * 1024; l < (chunk + 1) * 1024; l++)
        acc = fmaf(s_logit[l], h[base + (size_t)l * 256 + dch], acc);
    s_part[chunk * 256 + dch] = acc;
    __syncthreads();

    float val = 0.f;
    if (tid < 256) {
        const float pooled = (s_part[tid] + s_part[256 + tid] +
                              s_part[512 + tid] + s_part[768 + tid]) * inv;
        val = pooled * Wf[tid];
    }
    #pragma unroll
    for (int o = 16; o > 0; o >>= 1) val += __shfl_xor_sync(~0u, val, o);
    __syncthreads();
    if (tid < 256 && (tid & 31) == 0) s_red[tid >> 5] = val;
    __syncthreads();
    if (tid == 0) {
        float tot = 0.f;
        #pragma unroll
        for (int i = 0; i < 8; i++) tot += s_red[i];
        out[b] = tot + bf[0];
    }
}

// ---------------------------------------------------------------------------
// Launch
// ---------------------------------------------------------------------------
extern "C" void kernel_launch(void* const* d_in, const int* in_sizes, int n_in,
                              void* d_out, int out_size)
{
    const float* x      = (const float*)d_in[0];
    const float* Wp     = (const float*)d_in[1];
    const float* bp     = (const float*)d_in[2];
    const float* g0     = (const float*)d_in[3];
    const float* b0     = (const float*)d_in[4];
    const float* Wi     = (const float*)d_in[5];
    const float* conv_w = (const float*)d_in[6];
    const float* conv_b = (const float*)d_in[7];
    const float* Wx     = (const float*)d_in[8];
    const float* Wdt    = (const float*)d_in[9];
    const float* bdt    = (const float*)d_in[10];
    const float* A_log  = (const float*)d_in[11];
    const float* Dp     = (const float*)d_in[12];
    const float* Wo     = (const float*)d_in[13];
    const float* ln_g   = (const float*)d_in[14];
    const float* ln_b   = (const float*)d_in[15];
    const float* wa     = (const float*)d_in[16];
    const float* ba     = (const float*)d_in[17];
    const float* Wf     = (const float*)d_in[18];
    const float* bf     = (const float*)d_in[19];

    float *p_h, *p_t0, *p_xz, *p_u, *p_dt, *p_xdbc, *p_y;
    cudaGetSymbolAddress((void**)&p_h,    g_h);
    cudaGetSymbolAddress((void**)&p_t0,   g_t0);
    cudaGetSymbolAddress((void**)&p_xz,   g_xz);
    cudaGetSymbolAddress((void**)&p_u,    g_u);
    cudaGetSymbolAddress((void**)&p_dt,   g_dt);
    cudaGetSymbolAddress((void**)&p_xdbc, g_xdbc);
    cudaGetSymbolAddress((void**)&p_y,    g_y);

    // input projection (tensor) + LN
    tf32_gemm<1><<<dim3(2, 256), 256>>>(Dn, DINn, x, DINn, Wp, bp, p_t0, Dn);
    ln256_kernel<<<Mrows, 256>>>(p_t0, p_h, g0, b0);

    for (int l = 0; l < NLn; l++) {
        // xz = h @ Wi^T   (N=1024, K=256) — tensor
        tf32_gemm<0><<<dim3(8, 256), 256>>>(2 * DIn, Dn, p_h, Dn,
                                            Wi + (size_t)l * 2 * DIn * Dn,
                                            nullptr, p_xz, 2 * DIn);
        // depthwise causal conv + silu
        conv_silu_kernel<<<(Mrows * DIn) / 256, 256>>>(
            p_xz, conv_w + (size_t)l * DIn * DCn, conv_b + (size_t)l * DIn, p_u);
        // xdbc = u @ Wx^T   (N=48, K=512) — SIMT fp32 (keeps scan inputs exact-ish)
        sgemm_nt<0><<<dim3(1, 256), 256>>>(48, DIn, p_u, DIn,
                                           Wx + (size_t)l * 48 * DIn,
                                           nullptr, p_xdbc, 48);
        // dt = softplus(dtraw @ Wdt^T + bdt)   (N=512, K=16) — SIMT fp32
        sgemm_nt<2><<<dim3(4, 256), 256>>>(DIn, DTRn, p_xdbc, 48,
                                           Wdt + (size_t)l * DIn * DTRn,
                                           bdt + (size_t)l * DIn, p_dt, DIn);
        // selective scan + fused epilogue
        scan_kernel<<<Bn * 16, 512>>>(p_u, p_dt, p_xz, p_xdbc,
                                      A_log + (size_t)l * DIn * DSn,
                                      Dp + (size_t)l * DIn, p_y);
        // out = y @ Wo^T   (N=256, K=512) — tensor, then LN
        tf32_gemm<0><<<dim3(2, 256), 256>>>(Dn, DIn, p_y, DIn,
                                            Wo + (size_t)l * Dn * DIn,
                                            nullptr, p_t0, Dn);
        ln256_kernel<<<Mrows, 256>>>(p_t0, p_h,
                                     ln_g + (size_t)l * Dn, ln_b + (size_t)l * Dn);
    }

    pool_kernel<<<Bn, 1024>>>(p_h, wa, ba, Wf, bf, (float*)d_out);
}

// round 4
// speedup vs baseline: 1.6822x; 1.3590x over previous
#include <cuda_runtime.h>
#include <math.h>
#include <stdint.h>

// Problem constants
#define Bn   8
#define Ln   4096
#define DINn 64
#define Dn   256
#define NLn  2
#define DIn  512
#define DSn  16
#define DCn  4
#define DTRn 16
#define Mrows (Bn * Ln)   // 32768

#define C_CHUNKS 4
#define CH_LEN   1024     // Ln / C_CHUNKS
#define NCH      (Bn * DIn * DSn)   // 65536 channels

// ---------------------------------------------------------------------------
// Scratch (device globals — no runtime allocation allowed)
// ---------------------------------------------------------------------------
__device__ float g_h    [Mrows * Dn];
__device__ float g_t0   [Mrows * Dn];
__device__ float g_xz   [Mrows * 2 * DIn];
__device__ float g_u    [Mrows * DIn];
__device__ float g_dt   [Mrows * DIn];
__device__ float g_xdbc [Mrows * 48];
__device__ float g_y    [Mrows * DIn];
__device__ float g_P    [(C_CHUNKS - 1) * NCH];
__device__ float g_h0   [(C_CHUNKS - 1) * NCH];
__device__ float g_hini [C_CHUNKS * NCH];
__device__ float g_logit[Mrows];
__device__ float g_part [Bn * 16 * Dn];

// ---------------------------------------------------------------------------
// Helpers
// ---------------------------------------------------------------------------
__device__ __forceinline__ float softplus_f(float x) {
    return fmaxf(x, 0.f) + log1pf(__expf(-fabsf(x)));
}
__device__ __forceinline__ float silu_f(float x) {
    return x / (1.f + __expf(-x));
}
__device__ __forceinline__ float to_tf32(float x) {
    float r;
    asm("cvt.rna.tf32.f32 %0, %1;" : "=f"(r) : "f"(x));
    return r;
}
__device__ __forceinline__ void mma8(float* d,
                                     float a0, float a1, float a2, float a3,
                                     float b0, float b1) {
    asm volatile(
        "mma.sync.aligned.m16n8k8.row.col.f32.tf32.tf32.f32 "
        "{%0,%1,%2,%3},{%4,%5,%6,%7},{%8,%9},{%0,%1,%2,%3};"
        : "+f"(d[0]), "+f"(d[1]), "+f"(d[2]), "+f"(d[3])
        : "r"(__float_as_uint(a0)), "r"(__float_as_uint(a1)),
          "r"(__float_as_uint(a2)), "r"(__float_as_uint(a3)),
          "r"(__float_as_uint(b0)), "r"(__float_as_uint(b1)));
}

// ---------------------------------------------------------------------------
// TF32 tensor-core GEMM: C[M,N] = A[M,K] (row-major, lda) * W[N,K]^T.
// M%128==0, K%16==0. N arbitrary (guards on W loads + stores); grid.x covers
// ceil(N/128). Tile 128x128x16, 256 threads, warp tile 64x32 of m16n8k8.
// EPI: 0 = store, 1 = +bias
// ---------------------------------------------------------------------------
#define SPAD 24
template <int EPI>
__global__ void __launch_bounds__(256, 2) tf32_gemm(
    int N, int K,
    const float* __restrict__ A, int lda,
    const float* __restrict__ W,
    const float* __restrict__ bias,
    float* __restrict__ C, int ldc)
{
    __shared__ float As[2][128][SPAD];
    __shared__ float Ws[2][128][SPAD];

    const int tid  = threadIdx.x;
    const int wid  = tid >> 5, lane = tid & 31;
    const int wm   = (wid >> 2) * 64;
    const int wn   = (wid & 3) * 32;
    const int gr   = lane >> 2;
    const int gc   = lane & 3;
    const int m0   = blockIdx.y * 128;
    const int n0   = blockIdx.x * 128;

    const int lr0 = tid >> 2;
    const int lj  = tid & 3;
    const int pb  = (lj & 2) * 4 + (lj & 1);

    const float* Ag = A + (size_t)(m0 + lr0) * lda + lj * 4;
    const float* Wg = W + (size_t)(n0 + lr0) * K + lj * 4;
    const bool wok0 = (n0 + lr0) < N;
    const bool wok1 = (n0 + lr0 + 64) < N;

    float acc[4][4][4];
    #pragma unroll
    for (int i = 0; i < 4; i++)
        #pragma unroll
        for (int j = 0; j < 4; j++)
            #pragma unroll
            for (int t = 0; t < 4; t++) acc[i][j][t] = 0.f;

    float4 ra0, ra1, rw0, rw1;
    const float4 z4 = make_float4(0.f, 0.f, 0.f, 0.f);

    ra0 = *(const float4*)(Ag);
    ra1 = *(const float4*)(Ag + (size_t)64 * lda);
    rw0 = wok0 ? *(const float4*)(Wg) : z4;
    rw1 = wok1 ? *(const float4*)(Wg + (size_t)64 * K) : z4;
    {
        As[0][lr0     ][pb]     = to_tf32(ra0.x);
        As[0][lr0     ][pb + 2] = to_tf32(ra0.y);
        As[0][lr0     ][pb + 4] = to_tf32(ra0.z);
        As[0][lr0     ][pb + 6] = to_tf32(ra0.w);
        As[0][lr0 + 64][pb]     = to_tf32(ra1.x);
        As[0][lr0 + 64][pb + 2] = to_tf32(ra1.y);
        As[0][lr0 + 64][pb + 4] = to_tf32(ra1.z);
        As[0][lr0 + 64][pb + 6] = to_tf32(ra1.w);
        Ws[0][lr0     ][pb]     = to_tf32(rw0.x);
        Ws[0][lr0     ][pb + 2] = to_tf32(rw0.y);
        Ws[0][lr0     ][pb + 4] = to_tf32(rw0.z);
        Ws[0][lr0     ][pb + 6] = to_tf32(rw0.w);
        Ws[0][lr0 + 64][pb]     = to_tf32(rw1.x);
        Ws[0][lr0 + 64][pb + 2] = to_tf32(rw1.y);
        Ws[0][lr0 + 64][pb + 4] = to_tf32(rw1.z);
        Ws[0][lr0 + 64][pb + 6] = to_tf32(rw1.w);
    }
    __syncthreads();

    int buf = 0;
    for (int k0 = 16; k0 < K; k0 += 16) {
        ra0 = *(const float4*)(Ag + k0);
        ra1 = *(const float4*)(Ag + (size_t)64 * lda + k0);
        rw0 = wok0 ? *(const float4*)(Wg + k0) : z4;
        rw1 = wok1 ? *(const float4*)(Wg + (size_t)64 * K + k0) : z4;

        #pragma unroll
        for (int ks = 0; ks < 2; ks++) {
            float2 alo[4], ahi[4], bfr[4];
            #pragma unroll
            for (int fm = 0; fm < 4; fm++) {
                alo[fm] = *(const float2*)&As[buf][wm + fm * 16 + gr    ][ks * 8 + 2 * gc];
                ahi[fm] = *(const float2*)&As[buf][wm + fm * 16 + gr + 8][ks * 8 + 2 * gc];
            }
            #pragma unroll
            for (int fn = 0; fn < 4; fn++)
                bfr[fn] = *(const float2*)&Ws[buf][wn + fn * 8 + gr][ks * 8 + 2 * gc];
            #pragma unroll
            for (int fm = 0; fm < 4; fm++)
                #pragma unroll
                for (int fn = 0; fn < 4; fn++)
                    mma8(acc[fm][fn], alo[fm].x, ahi[fm].x, alo[fm].y, ahi[fm].y,
                         bfr[fn].x, bfr[fn].y);
        }

        const int nb = buf ^ 1;
        As[nb][lr0     ][pb]     = to_tf32(ra0.x);
        As[nb][lr0     ][pb + 2] = to_tf32(ra0.y);
        As[nb][lr0     ][pb + 4] = to_tf32(ra0.z);
        As[nb][lr0     ][pb + 6] = to_tf32(ra0.w);
        As[nb][lr0 + 64][pb]     = to_tf32(ra1.x);
        As[nb][lr0 + 64][pb + 2] = to_tf32(ra1.y);
        As[nb][lr0 + 64][pb + 4] = to_tf32(ra1.z);
        As[nb][lr0 + 64][pb + 6] = to_tf32(ra1.w);
        Ws[nb][lr0     ][pb]     = to_tf32(rw0.x);
        Ws[nb][lr0     ][pb + 2] = to_tf32(rw0.y);
        Ws[nb][lr0     ][pb + 4] = to_tf32(rw0.z);
        Ws[nb][lr0     ][pb + 6] = to_tf32(rw0.w);
        Ws[nb][lr0 + 64][pb]     = to_tf32(rw1.x);
        Ws[nb][lr0 + 64][pb + 2] = to_tf32(rw1.y);
        Ws[nb][lr0 + 64][pb + 4] = to_tf32(rw1.z);
        Ws[nb][lr0 + 64][pb + 6] = to_tf32(rw1.w);
        __syncthreads();
        buf = nb;
    }

    #pragma unroll
    for (int ks = 0; ks < 2; ks++) {
        float2 alo[4], ahi[4], bfr[4];
        #pragma unroll
        for (int fm = 0; fm < 4; fm++) {
            alo[fm] = *(const float2*)&As[buf][wm + fm * 16 + gr    ][ks * 8 + 2 * gc];
            ahi[fm] = *(const float2*)&As[buf][wm + fm * 16 + gr + 8][ks * 8 + 2 * gc];
        }
        #pragma unroll
        for (int fn = 0; fn < 4; fn++)
            bfr[fn] = *(const float2*)&Ws[buf][wn + fn * 8 + gr][ks * 8 + 2 * gc];
        #pragma unroll
        for (int fm = 0; fm < 4; fm++)
            #pragma unroll
            for (int fn = 0; fn < 4; fn++)
                mma8(acc[fm][fn], alo[fm].x, ahi[fm].x, alo[fm].y, ahi[fm].y,
                     bfr[fn].x, bfr[fn].y);
    }

    #pragma unroll
    for (int fm = 0; fm < 4; fm++) {
        const int r0 = m0 + wm + fm * 16 + gr;
        #pragma unroll
        for (int fn = 0; fn < 4; fn++) {
            const int c0 = n0 + wn + fn * 8 + 2 * gc;
            if (c0 < N) {
                float v0 = acc[fm][fn][0], v1 = acc[fm][fn][1];
                float v2 = acc[fm][fn][2], v3 = acc[fm][fn][3];
                if (EPI == 1) {
                    v0 += bias[c0]; v1 += bias[c0 + 1];
                    v2 += bias[c0]; v3 += bias[c0 + 1];
                }
                *(float2*)&C[(size_t)r0 * ldc + c0]       = make_float2(v0, v1);
                *(float2*)&C[(size_t)(r0 + 8) * ldc + c0] = make_float2(v2, v3);
            }
        }
    }
}

// ---------------------------------------------------------------------------
// SIMT SGEMM (dt only: N=512, K=16 — tiny-K, memory-ish).
// EPI: 2 = softplus(+bias)
// ---------------------------------------------------------------------------
template <int EPI>
__global__ void __launch_bounds__(256, 2) sgemm_nt(
    int N, int K,
    const float* __restrict__ A, int lda,
    const float* __restrict__ W,
    const float* __restrict__ bias,
    float* __restrict__ C, int ldc)
{
    __shared__ __align__(16) float As[8][132];
    __shared__ __align__(16) float Ws2[8][132];

    const int tid = threadIdx.x;
    const int tx = tid & 15;
    const int ty = tid >> 4;
    const int m0 = blockIdx.y * 128;
    const int n0 = blockIdx.x * 128;

    const int lr = tid >> 1;
    const int lk = (tid & 1) * 4;

    float acc[8][8];
    #pragma unroll
    for (int i = 0; i < 8; i++)
        #pragma unroll
        for (int j = 0; j < 8; j++) acc[i][j] = 0.f;

    const float* Aptr = A + (size_t)(m0 + lr) * lda + lk;
    const int wn = n0 + lr;
    const float* Wptr = W + (size_t)wn * K + lk;
    const bool wok = (wn < N);

    for (int k0 = 0; k0 < K; k0 += 8) {
        float4 av = *(const float4*)(Aptr + k0);
        As[lk + 0][lr] = av.x; As[lk + 1][lr] = av.y;
        As[lk + 2][lr] = av.z; As[lk + 3][lr] = av.w;

        float4 wv = make_float4(0.f, 0.f, 0.f, 0.f);
        if (wok) wv = *(const float4*)(Wptr + k0);
        Ws2[lk + 0][lr] = wv.x; Ws2[lk + 1][lr] = wv.y;
        Ws2[lk + 2][lr] = wv.z; Ws2[lk + 3][lr] = wv.w;

        __syncthreads();
        #pragma unroll
        for (int k = 0; k < 8; k++) {
            float a[8], bb[8];
            *(float4*)&a[0]  = *(const float4*)&As[k][ty * 4];
            *(float4*)&a[4]  = *(const float4*)&As[k][64 + ty * 4];
            *(float4*)&bb[0] = *(const float4*)&Ws2[k][tx * 4];
            *(float4*)&bb[4] = *(const float4*)&Ws2[k][64 + tx * 4];
            #pragma unroll
            for (int i = 0; i < 8; i++)
                #pragma unroll
                for (int j = 0; j < 8; j++)
                    acc[i][j] = fmaf(a[i], bb[j], acc[i][j]);
        }
        __syncthreads();
    }

    #pragma unroll
    for (int i = 0; i < 8; i++) {
        const int r = m0 + ((i < 4) ? (ty * 4 + i) : (64 + ty * 4 + i - 4));
        #pragma unroll
        for (int j = 0; j < 8; j++) {
            const int c = n0 + ((j < 4) ? (tx * 4 + j) : (64 + tx * 4 + j - 4));
            if (c < N) {
                float v = acc[i][j];
                if (EPI >= 1) v += bias[c];
                if (EPI == 2) v = softplus_f(v);
                C[(size_t)r * ldc + c] = v;
            }
        }
    }
}

// ---------------------------------------------------------------------------
// Depthwise causal conv (DC=4) + bias + SiLU.  Reads u-half of g_xz.
// ---------------------------------------------------------------------------
__global__ void conv_silu_kernel(const float* __restrict__ xz,
                                 const float* __restrict__ w,
                                 const float* __restrict__ cb,
                                 float* __restrict__ u)
{
    const int idx = blockIdx.x * blockDim.x + threadIdx.x;
    if (idx >= Mrows * DIn) return;
    const int d  = idx & (DIn - 1);
    const int bl = idx >> 9;
    const int l  = bl & (Ln - 1);
    float acc = cb[d];
    #pragma unroll
    for (int k = 0; k < 4; k++) {
        const int ll = l - 3 + k;
        if (ll >= 0)
            acc = fmaf(w[d * 4 + k], xz[(size_t)(bl - 3 + k) * (2 * DIn) + d], acc);
    }
    u[idx] = silu_f(acc);
}

// ---------------------------------------------------------------------------
// LayerNorm over last dim (256), one block per row.
// ---------------------------------------------------------------------------
__global__ void ln256_kernel(const float* __restrict__ in, float* __restrict__ out,
                             const float* __restrict__ g, const float* __restrict__ b)
{
    const int row = blockIdx.x;
    const int t = threadIdx.x;
    const float v = in[(size_t)row * 256 + t];
    float s = v, sq = v * v;
    #pragma unroll
    for (int o = 16; o > 0; o >>= 1) {
        s  += __shfl_xor_sync(~0u, s, o);
        sq += __shfl_xor_sync(~0u, sq, o);
    }
    __shared__ float ss[8], ssq[8];
    if ((t & 31) == 0) { ss[t >> 5] = s; ssq[t >> 5] = sq; }
    __syncthreads();
    float tot = 0.f, totq = 0.f;
    #pragma unroll
    for (int i = 0; i < 8; i++) { tot += ss[i]; totq += ssq[i]; }
    const float mean = tot * (1.f / 256.f);
    const float var  = totq * (1.f / 256.f) - mean * mean;
    const float rstd = rsqrtf(var + 1e-5f);
    out[(size_t)row * 256 + t] = (v - mean) * rstd * g[t] + b[t];
}

// ---------------------------------------------------------------------------
// Chunked selective scan.
// Pass 1 (carry): per chunk c in [0, C-2], compute P = prod(dA), h0 = local
//   scan from 0.  Light: no z, no y, no shfl.
// Pass 2 (fix): compose carries sequentially -> h_init per chunk.
// Pass 3 (main): full scan per chunk starting from h_init, fused epilogue.
// Thread mapping everywhere: block 512 = 32 d x 16 s; s = lane bits[0:4).
// ---------------------------------------------------------------------------
#define SCH 64

__global__ void __launch_bounds__(512) scan_carry_kernel(
    const float* __restrict__ u, const float* __restrict__ dt,
    const float* __restrict__ xdbc, const float* __restrict__ A_log,
    float* __restrict__ Pout, float* __restrict__ h0out)
{
    __shared__ float s_dt[SCH][32], s_u[SCH][32], s_B[SCH][16];

    const int tid = threadIdx.x;
    const int c   = blockIdx.x >> 7;          // 0..C-2
    const int rem = blockIdx.x & 127;
    const int b   = rem >> 4;
    const int d0  = (rem & 15) * 32;
    const int s   = tid & 15;
    const int dd  = tid >> 4;
    const int d   = d0 + dd;

    const float A = -__expf(A_log[d * DSn + s]);
    float h = 0.f, P = 1.f;

    const size_t base_bl = (size_t)b * Ln + (size_t)c * CH_LEN;

    for (int l0 = 0; l0 < CH_LEN; l0 += SCH) {
        for (int i = tid; i < SCH * 32; i += 512) {
            const int r = i >> 5, cc = i & 31;
            const size_t bl = base_bl + l0 + r;
            s_dt[r][cc] = dt[bl * DIn + d0 + cc];
            s_u [r][cc] = u [bl * DIn + d0 + cc];
        }
        for (int i = tid; i < SCH * 16; i += 512) {
            const int r = i >> 4, cc = i & 15;
            const size_t bl = base_bl + l0 + r;
            s_B[r][cc] = xdbc[bl * 48 + 16 + cc];
        }
        __syncthreads();

        #pragma unroll 4
        for (int i = 0; i < SCH; i++) {
            const float dtv = s_dt[i][dd];
            const float dA  = __expf(dtv * A);
            P *= dA;
            h = fmaf(h, dA, dtv * s_u[i][dd] * s_B[i][s]);
        }
        __syncthreads();
    }

    const int ch = ((b * DIn + d) * DSn + s);
    Pout [c * NCH + ch] = P;
    h0out[c * NCH + ch] = h;
}

__global__ void scan_fix_kernel(const float* __restrict__ P,
                                const float* __restrict__ h0,
                                float* __restrict__ hini)
{
    const int ch = blockIdx.x * blockDim.x + threadIdx.x;
    float h = 0.f;
    hini[ch] = 0.f;
    #pragma unroll
    for (int c = 1; c < C_CHUNKS; c++) {
        h = fmaf(P[(c - 1) * NCH + ch], h, h0[(c - 1) * NCH + ch]);
        hini[c * NCH + ch] = h;
    }
}

__global__ void __launch_bounds__(512) scan_main_kernel(
    const float* __restrict__ u, const float* __restrict__ dt,
    const float* __restrict__ xz, const float* __restrict__ xdbc,
    const float* __restrict__ A_log, const float* __restrict__ Dp,
    const float* __restrict__ hini,
    float* __restrict__ y)
{
    __shared__ float s_dt[SCH][32], s_u[SCH][32], s_z[SCH][32], s_y[SCH][32];
    __shared__ float s_B[SCH][16], s_C[SCH][16];

    const int tid = threadIdx.x;
    const int c   = blockIdx.x >> 7;          // 0..C-1
    const int rem = blockIdx.x & 127;
    const int b   = rem >> 4;
    const int d0  = (rem & 15) * 32;
    const int s   = tid & 15;
    const int dd  = tid >> 4;
    const int d   = d0 + dd;

    const float A   = -__expf(A_log[d * DSn + s]);
    const float dpv = Dp[d];
    const int ch = ((b * DIn + d) * DSn + s);
    float h = hini[c * NCH + ch];

    const size_t base_bl = (size_t)b * Ln + (size_t)c * CH_LEN;

    for (int l0 = 0; l0 < CH_LEN; l0 += SCH) {
        for (int i = tid; i < SCH * 32; i += 512) {
            const int r = i >> 5, cc = i & 31;
            const size_t bl = base_bl + l0 + r;
            s_dt[r][cc] = dt[bl * DIn + d0 + cc];
            s_u [r][cc] = u [bl * DIn + d0 + cc];
            s_z [r][cc] = xz[bl * (2 * DIn) + DIn + d0 + cc];
        }
        for (int i = tid; i < SCH * 16; i += 512) {
            const int r = i >> 4, cc = i & 15;
            const size_t bl = base_bl + l0 + r;
            s_B[r][cc] = xdbc[bl * 48 + 16 + cc];
            s_C[r][cc] = xdbc[bl * 48 + 32 + cc];
        }
        __syncthreads();

        #pragma unroll 4
        for (int i = 0; i < SCH; i++) {
            const float dtv = s_dt[i][dd];
            const float uv  = s_u[i][dd];
            const float dA  = __expf(dtv * A);
            h = fmaf(h, dA, dtv * uv * s_B[i][s]);
            float yv = h * s_C[i][s];
            yv += __shfl_xor_sync(~0u, yv, 1);
            yv += __shfl_xor_sync(~0u, yv, 2);
            yv += __shfl_xor_sync(~0u, yv, 4);
            yv += __shfl_xor_sync(~0u, yv, 8);
            if (s == 0) {
                const float zv = s_z[i][dd];
                s_y[i][dd] = (yv + uv * dpv) * silu_f(zv);
            }
        }
        __syncthreads();

        for (int i = tid; i < SCH * 32; i += 512) {
            const int r = i >> 5, cc = i & 31;
            y[(base_bl + l0 + r) * DIn + d0 + cc] = s_y[r][cc];
        }
        __syncthreads();
    }
}

// ---------------------------------------------------------------------------
// Pooling, split for chip-wide bandwidth.
// ---------------------------------------------------------------------------
__global__ void pool_logit_kernel(const float* __restrict__ h,
                                  const float* __restrict__ wa,
                                  const float* __restrict__ ba,
                                  float* __restrict__ logit)
{
    const int wid_in_blk = threadIdx.x >> 5;
    const int lane = threadIdx.x & 31;
    const int row = blockIdx.x * 8 + wid_in_blk;
    const float* r = h + (size_t)row * 256;
    float acc = 0.f;
    #pragma unroll
    for (int k = 0; k < 2; k++) {
        const float4 hv = *(const float4*)(r + k * 128 + lane * 4);
        const float4 wv = *(const float4*)(wa + k * 128 + lane * 4);
        acc += hv.x * wv.x + hv.y * wv.y + hv.z * wv.z + hv.w * wv.w;
    }
    #pragma unroll
    for (int o = 16; o > 0; o >>= 1) acc += __shfl_xor_sync(~0u, acc, o);
    if (lane == 0) logit[row] = acc + ba[0];
}

__global__ void __launch_bounds__(1024) pool_softmax_kernel(float* __restrict__ logit)
{
    __shared__ float s_red[32];
    const int b = blockIdx.x, tid = threadIdx.x;
    float* lg = logit + b * Ln;

    float mx = -1e30f;
    float v[4];
    #pragma unroll
    for (int k = 0; k < 4; k++) {
        v[k] = lg[tid + k * 1024];
        mx = fmaxf(mx, v[k]);
    }
    #pragma unroll
    for (int o = 16; o > 0; o >>= 1) mx = fmaxf(mx, __shfl_xor_sync(~0u, mx, o));
    if ((tid & 31) == 0) s_red[tid >> 5] = mx;
    __syncthreads();
    if (tid < 32) {
        float t = s_red[tid];
        #pragma unroll
        for (int o = 16; o > 0; o >>= 1) t = fmaxf(t, __shfl_xor_sync(~0u, t, o));
        s_red[tid] = t;
    }
    __syncthreads();
    mx = s_red[0];
    __syncthreads();

    float sum = 0.f;
    #pragma unroll
    for (int k = 0; k < 4; k++) {
        v[k] = __expf(v[k] - mx);
        sum += v[k];
    }
    #pragma unroll
    for (int o = 16; o > 0; o >>= 1) sum += __shfl_xor_sync(~0u, sum, o);
    if ((tid & 31) == 0) s_red[tid >> 5] = sum;
    __syncthreads();
    if (tid < 32) {
        float t = s_red[tid];
        #pragma unroll
        for (int o = 16; o > 0; o >>= 1) t += __shfl_xor_sync(~0u, t, o);
        s_red[tid] = t;
    }
    __syncthreads();
    const float inv = 1.f / s_red[0];
    #pragma unroll
    for (int k = 0; k < 4; k++) lg[tid + k * 1024] = v[k] * inv;
}

__global__ void pool_wsum_kernel(const float* __restrict__ h,
                                 const float* __restrict__ p,
                                 float* __restrict__ part)
{
    const int b = blockIdx.x >> 4;
    const int sp = blockIdx.x & 15;
    const int tid = threadIdx.x;   // 256
    const size_t base = ((size_t)b * Ln + sp * 256) * 256;
    const float* pp = p + b * Ln + sp * 256;
    float acc = 0.f;
    for (int l = 0; l < 256; l++)
        acc = fmaf(pp[l], h[base + (size_t)l * 256 + tid], acc);
    part[(size_t)(b * 16 + sp) * 256 + tid] = acc;
}

__global__ void pool_final_kernel(const float* __restrict__ part,
                                  const float* __restrict__ Wf,
                                  const float* __restrict__ bf,
                                  float* __restrict__ out)
{
    __shared__ float s_red[8];
    const int b = blockIdx.x, tid = threadIdx.x;   // 256
    float pooled = 0.f;
    #pragma unroll
    for (int sp = 0; sp < 16; sp++)
        pooled += part[(size_t)(b * 16 + sp) * 256 + tid];
    float val = pooled * Wf[tid];
    #pragma unroll
    for (int o = 16; o > 0; o >>= 1) val += __shfl_xor_sync(~0u, val, o);
    if ((tid & 31) == 0) s_red[tid >> 5] = val;
    __syncthreads();
    if (tid == 0) {
        float tot = 0.f;
        #pragma unroll
        for (int i = 0; i < 8; i++) tot += s_red[i];
        out[b] = tot + bf[0];
    }
}

// ---------------------------------------------------------------------------
// Launch
// ---------------------------------------------------------------------------
extern "C" void kernel_launch(void* const* d_in, const int* in_sizes, int n_in,
                              void* d_out, int out_size)
{
    const float* x      = (const float*)d_in[0];
    const float* Wp     = (const float*)d_in[1];
    const float* bp     = (const float*)d_in[2];
    const float* g0     = (const float*)d_in[3];
    const float* b0     = (const float*)d_in[4];
    const float* Wi     = (const float*)d_in[5];
    const float* conv_w = (const float*)d_in[6];
    const float* conv_b = (const float*)d_in[7];
    const float* Wx     = (const float*)d_in[8];
    const float* Wdt    = (const float*)d_in[9];
    const float* bdt    = (const float*)d_in[10];
    const float* A_log  = (const float*)d_in[11];
    const float* Dp     = (const float*)d_in[12];
    const float* Wo     = (const float*)d_in[13];
    const float* ln_g   = (const float*)d_in[14];
    const float* ln_b   = (const float*)d_in[15];
    const float* wa     = (const float*)d_in[16];
    const float* ba     = (const float*)d_in[17];
    const float* Wf     = (const float*)d_in[18];
    const float* bf     = (const float*)d_in[19];

    float *p_h, *p_t0, *p_xz, *p_u, *p_dt, *p_xdbc, *p_y;
    float *p_P, *p_h0, *p_hini, *p_logit, *p_part;
    cudaGetSymbolAddress((void**)&p_h,    g_h);
    cudaGetSymbolAddress((void**)&p_t0,   g_t0);
    cudaGetSymbolAddress((void**)&p_xz,   g_xz);
    cudaGetSymbolAddress((void**)&p_u,    g_u);
    cudaGetSymbolAddress((void**)&p_dt,   g_dt);
    cudaGetSymbolAddress((void**)&p_xdbc, g_xdbc);
    cudaGetSymbolAddress((void**)&p_y,    g_y);
    cudaGetSymbolAddress((void**)&p_P,    g_P);
    cudaGetSymbolAddress((void**)&p_h0,   g_h0);
    cudaGetSymbolAddress((void**)&p_hini, g_hini);
    cudaGetSymbolAddress((void**)&p_logit, g_logit);
    cudaGetSymbolAddress((void**)&p_part, g_part);

    // input projection + bias (tensor) + LN
    tf32_gemm<1><<<dim3(2, 256), 256>>>(Dn, DINn, x, DINn, Wp, bp, p_t0, Dn);
    ln256_kernel<<<Mrows, 256>>>(p_t0, p_h, g0, b0);

    for (int l = 0; l < NLn; l++) {
        // xz = h @ Wi^T  (N=1024, K=256) — tensor
        tf32_gemm<0><<<dim3(8, 256), 256>>>(2 * DIn, Dn, p_h, Dn,
                                            Wi + (size_t)l * 2 * DIn * Dn,
                                            nullptr, p_xz, 2 * DIn);
        // depthwise causal conv + silu
        conv_silu_kernel<<<(Mrows * DIn) / 256, 256>>>(
            p_xz, conv_w + (size_t)l * DIn * DCn, conv_b + (size_t)l * DIn, p_u);
        // xdbc = u @ Wx^T  (N=48, K=512) — tensor w/ N guard
        tf32_gemm<0><<<dim3(1, 256), 256>>>(48, DIn, p_u, DIn,
                                            Wx + (size_t)l * 48 * DIn,
                                            nullptr, p_xdbc, 48);
        // dt = softplus(dtraw @ Wdt^T + bdt)  (N=512, K=16) — SIMT
        sgemm_nt<2><<<dim3(4, 256), 256>>>(DIn, DTRn, p_xdbc, 48,
                                           Wdt + (size_t)l * DIn * DTRn,
                                           bdt + (size_t)l * DIn, p_dt, DIn);
        // chunked selective scan
        scan_carry_kernel<<<128 * (C_CHUNKS - 1), 512>>>(
            p_u, p_dt, p_xdbc, A_log + (size_t)l * DIn * DSn, p_P, p_h0);
        scan_fix_kernel<<<NCH / 256, 256>>>(p_P, p_h0, p_hini);
        scan_main_kernel<<<128 * C_CHUNKS, 512>>>(
            p_u, p_dt, p_xz, p_xdbc,
            A_log + (size_t)l * DIn * DSn, Dp + (size_t)l * DIn,
            p_hini, p_y);
        // out = y @ Wo^T  (N=256, K=512) — tensor, then LN
        tf32_gemm<0><<<dim3(2, 256), 256>>>(Dn, DIn, p_y, DIn,
                                            Wo + (size_t)l * Dn * DIn,
                                            nullptr, p_t0, Dn);
        ln256_kernel<<<Mrows, 256>>>(p_t0, p_h,
                                     ln_g + (size_t)l * Dn, ln_b + (size_t)l * Dn);
    }

    // pooling + final linear
    pool_logit_kernel<<<Mrows / 8, 256>>>(p_h, wa, ba, p_logit);
    pool_softmax_kernel<<<Bn, 1024>>>(p_logit);
    pool_wsum_kernel<<<Bn * 16, 256>>>(p_h, p_logit, p_part);
    pool_final_kernel<<<Bn, 256>>>(p_part, Wf, bf, (float*)d_out);
}